// round 2
// baseline (speedup 1.0000x reference)
#include <cuda_runtime.h>

#define NW 14
#define NSTATE (1 << NW)        // 16384 amplitudes
#define NTHREADS 1024
#define NWARPS (NTHREADS / 32)

// GF(2) description of the CNOT-ring entangler:
//  u = A x : virtual bit values after one entangler; gate on virtual bit b pairs
//  indices differing by column b of A^-1; measurement (after A^2) uses rows of A^2.
struct GateMasks {
    int rowA[NW];      // rows of A (base parities)
    int colAinv[NW];   // columns of A^-1 (pair masks)
    int rowA2[NW];     // rows of A^2 (measurement parity masks)
    int pos[4][12];    // complement unit positions per pass (passes 0-2: 10, pass 3: 12)
    int sel0, sel1;    // pass-D WHT selector bits per wire
};

__device__ __forceinline__ float2 cmul(float2 a, float2 b) {
    return make_float2(fmaf(a.x, b.x, -a.y * b.y), fmaf(a.x, b.y, a.y * b.x));
}
__device__ __forceinline__ float2 cmadd(float2 acc, float2 a, float2 b) {
    acc.x = fmaf(a.x, b.x, fmaf(-a.y, b.y, acc.x));
    acc.y = fmaf(a.x, b.y, fmaf(a.y, b.x, acc.y));
    return acc;
}
// Bank-conflict swizzle: fold address bits 4..7 into 0..3 (involution-free bijection).
__device__ __forceinline__ int swz(int y) { return y ^ ((y >> 4) & 0xF); }
__device__ __forceinline__ int par(int v) { return __popc(v) & 1; }

__global__ __launch_bounds__(NTHREADS, 1)
void qsim_kernel(const float* __restrict__ x, const float* __restrict__ params,
                 float* __restrict__ out, GateMasks gm)
{
    extern __shared__ float2 state[];      // 16384 float2 = 128 KB
    __shared__ float2 mats[2][NW][4];      // fused 2x2 per (layer, wire)
    __shared__ int Tlo[128], Thi[128];     // packed 14-wire parity LUTs
    __shared__ float wsum[NWARPS][NW];

    const int tid = threadIdx.x;
    const int b = blockIdx.x;

    // ---- 0a. Fused gate matrices: M = RX * RZ * RY (layer 0 folds in x)
    if (tid < 2 * NW) {
        const int l = tid / NW, w = tid % NW;
        const float* pp = params + (l * NW + w) * 3;
        float th = pp[0] + (l == 0 ? x[b * NW + w] : 0.0f);
        float s, c;   sincosf(0.5f * th, &s, &c);
        float sz, cz; sincosf(0.5f * pp[1], &sz, &cz);
        float sx, cx; sincosf(0.5f * pp[2], &sx, &cx);
        float2 r00 = make_float2(c * cz, -c * sz);
        float2 r01 = make_float2(-s * cz, s * sz);
        float2 r10 = make_float2(s * cz, s * sz);
        float2 r11 = make_float2(c * cz, c * sz);
        mats[l][w][0] = make_float2(cx * r00.x + sx * r10.y, cx * r00.y - sx * r10.x);
        mats[l][w][1] = make_float2(cx * r01.x + sx * r11.y, cx * r01.y - sx * r11.x);
        mats[l][w][2] = make_float2(sx * r00.y + cx * r10.x, -sx * r00.x + cx * r10.y);
        mats[l][w][3] = make_float2(sx * r01.y + cx * r11.x, -sx * r01.x + cx * r11.y);
    }
    // ---- 0b. Parity LUTs: bit w of Tlo[i]^Thi[j] = parity((i | j<<7) & rowA2[13-w])
    if (tid >= 64 && tid < 192) {
        const int i = tid - 64;
        int v = 0;
#pragma unroll
        for (int w = 0; w < NW; ++w) v |= par(i & (gm.rowA2[13 - w] & 0x7F)) << w;
        Tlo[i] = v;
    }
    if (tid >= 192 && tid < 320) {
        const int i = tid - 192;
        int v = 0;
#pragma unroll
        for (int w = 0; w < NW; ++w) v |= par(i & ((gm.rowA2[13 - w] >> 7) & 0x7F)) << w;
        Thi[i] = v;
    }
    __syncthreads();

    // ---- 1. Pass 0: build post-layer-0 product state directly (no loads)
    {
        const int t = tid;  // high 10 bits of y
        float2 p = mats[0][9][(t & 1) ? 2 : 0];        // y bit 4 = wire 9
#pragma unroll
        for (int bb = 5; bb < 14; ++bb) {
            float2 c = mats[0][13 - bb][((t >> (bb - 4)) & 1) ? 2 : 0];
            p = cmul(p, c);
        }
        float2 amp[16];
        amp[0] = p;
#pragma unroll
        for (int i = 0; i < 4; ++i) {                  // y bit i = wire 13-i
            const float2 c0 = mats[0][13 - i][0], c1 = mats[0][13 - i][2];
#pragma unroll
            for (int j = (1 << i) - 1; j >= 0; --j) {
                amp[j | (1 << i)] = cmul(amp[j], c1);
                amp[j] = cmul(amp[j], c0);
            }
        }
#pragma unroll
        for (int j = 0; j < 16; ++j) state[swz((t << 4) | j)] = amp[j];
    }
    __syncthreads();

    // ---- 2. Three 4-bit gate passes over virtual bits {10..13}, {6..9}, {2..5}
    for (int pidx = 0; pidx < 3; ++pidx) {
        const int B0 = 10 - 4 * pidx;
        const int* pos = gm.pos[pidx];
        int r = 0;
#pragma unroll
        for (int k = 0; k < 10; ++k) r |= ((tid >> k) & 1) << pos[k];
        const int m0 = gm.colAinv[B0],     m1 = gm.colAinv[B0 + 1];
        const int m2 = gm.colAinv[B0 + 2], m3 = gm.colAinv[B0 + 3];
        const int base = par(r & gm.rowA[B0])            | (par(r & gm.rowA[B0 + 1]) << 1)
                       | (par(r & gm.rowA[B0 + 2]) << 2) | (par(r & gm.rowA[B0 + 3]) << 3);
        int mb = 0;
        if (base & 1) mb ^= m0;
        if (base & 2) mb ^= m1;
        if (base & 4) mb ^= m2;
        if (base & 8) mb ^= m3;

        float2 amp[16];
        int y = r ^ mb;                    // y(u) = (r^mb) ^ masks(u); gray-code walk
#pragma unroll
        for (int k = 0; k < 16; ++k) {
            const int u = k ^ (k >> 1);
            amp[u] = state[swz(y)];
            if (k < 15) {
                const int tz = ((k + 1) & 1) ? 0 : ((k + 1) & 2) ? 1 : ((k + 1) & 4) ? 2 : 3;
                y ^= (tz == 0) ? m0 : (tz == 1) ? m1 : (tz == 2) ? m2 : m3;
            }
        }
#pragma unroll
        for (int i = 0; i < 4; ++i) {
            const int w = 13 - (B0 + i);
            const float2 M00 = mats[1][w][0], M01 = mats[1][w][1];
            const float2 M10 = mats[1][w][2], M11 = mats[1][w][3];
#pragma unroll
            for (int u = 0; u < 16; ++u) {
                if (u & (1 << i)) continue;
                float2 a0 = amp[u], a1 = amp[u | (1 << i)];
                float2 n0 = cmul(M00, a0); n0 = cmadd(n0, M01, a1);
                float2 n1 = cmul(M10, a0); n1 = cmadd(n1, M11, a1);
                amp[u] = n0; amp[u | (1 << i)] = n1;
            }
        }
        __syncthreads();   // all loads done before any store of this pass? NO — see note
        y = r ^ mb;
#pragma unroll
        for (int k = 0; k < 16; ++k) {
            const int u = k ^ (k >> 1);
            state[swz(y)] = amp[u];
            if (k < 15) {
                const int tz = ((k + 1) & 1) ? 0 : ((k + 1) & 2) ? 1 : ((k + 1) & 4) ? 2 : 3;
                y ^= (tz == 0) ? m0 : (tz == 1) ? m1 : (tz == 2) ? m2 : m3;
            }
        }
        __syncthreads();
    }
    // NOTE: each pass loads/stores the same disjoint coset per thread, but the
    // mid-pass __syncthreads above guards cross-thread WAR between a thread's
    // stores and other threads' loads of the NEXT pass is handled by the tail
    // sync; the mid sync is not strictly required for intra-pass (cosets are
    // thread-private) — it is kept to separate this pass's stores from other
    // threads' still-outstanding loads of the same pass (same addresses, own
    // coset only, so actually private; cost is negligible).

    // ---- 3. Final pass: gates on virtual bits {0,1} fused with measurement
    float acc[NW];
#pragma unroll
    for (int w = 0; w < NW; ++w) acc[w] = 0.0f;
    {
        const int m0 = gm.colAinv[0], m1 = gm.colAinv[1];
        const float2 A00 = mats[1][13][0], A01 = mats[1][13][1];
        const float2 A10 = mats[1][13][2], A11 = mats[1][13][3];
        const float2 B00 = mats[1][12][0], B01 = mats[1][12][1];
        const float2 B10 = mats[1][12][2], B11 = mats[1][12][3];
#pragma unroll
        for (int it = 0; it < 4; ++it) {
            const int idx = tid + it * NTHREADS;
            int r = 0;
#pragma unroll
            for (int k = 0; k < 12; ++k) r |= ((idx >> k) & 1) << gm.pos[3][k];
            const int base = par(r & gm.rowA[0]) | (par(r & gm.rowA[1]) << 1);
            int mb = 0;
            if (base & 1) mb ^= m0;
            if (base & 2) mb ^= m1;
            const int y0 = r ^ mb;
            float2 a0 = state[swz(y0)];
            float2 a1 = state[swz(y0 ^ m0)];
            float2 a2 = state[swz(y0 ^ m1)];
            float2 a3 = state[swz(y0 ^ m1 ^ m0)];
            // gate wire 13 (virtual bit 0): pairs (a0,a1), (a2,a3)
            { float2 n0 = cmul(A00, a0); n0 = cmadd(n0, A01, a1);
              float2 n1 = cmul(A10, a0); n1 = cmadd(n1, A11, a1); a0 = n0; a1 = n1; }
            { float2 n0 = cmul(A00, a2); n0 = cmadd(n0, A01, a3);
              float2 n1 = cmul(A10, a2); n1 = cmadd(n1, A11, a3); a2 = n0; a3 = n1; }
            // gate wire 12 (virtual bit 1): pairs (a0,a2), (a1,a3)
            { float2 n0 = cmul(B00, a0); n0 = cmadd(n0, B01, a2);
              float2 n1 = cmul(B10, a0); n1 = cmadd(n1, B11, a2); a0 = n0; a2 = n1; }
            { float2 n0 = cmul(B00, a1); n0 = cmadd(n0, B01, a3);
              float2 n1 = cmul(B10, a1); n1 = cmadd(n1, B11, a3); a1 = n0; a3 = n1; }
            const float p0 = fmaf(a0.x, a0.x, a0.y * a0.y);
            const float p1 = fmaf(a1.x, a1.x, a1.y * a1.y);
            const float p2 = fmaf(a2.x, a2.x, a2.y * a2.y);
            const float p3 = fmaf(a3.x, a3.x, a3.y * a3.y);
            const float sa = p0 + p1, sb = p0 - p1, sc = p2 + p3, sd = p2 - p3;
            const float W0 = sa + sc, W1 = sb + sd, W2 = sa - sc, W3 = sb - sd;
            const int bp = Tlo[y0 & 127] ^ Thi[(y0 >> 7) & 127];
#pragma unroll
            for (int w = 0; w < NW; ++w) {
                const bool s0 = (gm.sel0 >> w) & 1;
                const bool s1 = (gm.sel1 >> w) & 1;
                const float tv = s1 ? (s0 ? W3 : W2) : (s0 ? W1 : W0);
                acc[w] += __int_as_float(__float_as_int(tv) ^
                                         (((unsigned)(bp >> w) & 1u) << 31));
            }
        }
    }

    // ---- 4. Block reduction of 14 accumulators
    const int lane = tid & 31, warp = tid >> 5;
#pragma unroll
    for (int w = 0; w < NW; ++w) {
        float v = acc[w];
#pragma unroll
        for (int off = 16; off; off >>= 1) v += __shfl_down_sync(0xFFFFFFFFu, v, off);
        if (lane == 0) wsum[warp][w] = v;
    }
    __syncthreads();
    if (tid < NW) {
        float s = 0.0f;
#pragma unroll
        for (int q = 0; q < NWARPS; ++q) s += wsum[q][tid];
        out[b * NW + tid] = s;
    }
}

// ---------------- host side ----------------

static int gf2par(unsigned v) { return __builtin_popcount(v) & 1; }

static bool invertibleSub(const int* cols, int k, int Tmask)
{
    int rows[4], n = 0;
    for (int p = 0; p < NW && n < k; ++p) if ((Tmask >> p) & 1) rows[n++] = p;
    unsigned mat[4];
    for (int i = 0; i < k; ++i) {
        unsigned m = 0;
        for (int j = 0; j < k; ++j) m |= (unsigned)((cols[j] >> rows[i]) & 1) << j;
        mat[i] = m;
    }
    for (int c = 0; c < k; ++c) {
        int piv = -1;
        for (int rr = c; rr < k; ++rr) if ((mat[rr] >> c) & 1) { piv = rr; break; }
        if (piv < 0) return false;
        unsigned tmp = mat[c]; mat[c] = mat[piv]; mat[piv] = tmp;
        for (int rr = 0; rr < k; ++rr)
            if (rr != c && ((mat[rr] >> c) & 1)) mat[rr] ^= mat[c];
    }
    return true;
}

// Choose removal set T (|T|=k): submatrix must be invertible (correctness);
// prefer a complement whose 4 lowest unit positions are <8 with distinct (p mod 4)
// so half-warp shared accesses stay bank-conflict-free under the swizzle.
static int chooseT(const int* cols, int k)
{
    int fallback = -1;
    for (int mask = 0; mask < (1 << NW); ++mask) {
        if (__builtin_popcount((unsigned)mask) != k) continue;
        if (!invertibleSub(cols, k, mask)) continue;
        int arr[NW], n = 0;
        for (int p = 0; p < NW; ++p) if (!((mask >> p) & 1)) arr[n++] = p;
        bool cf = arr[0] < 8 && arr[1] < 8 && arr[2] < 8 && arr[3] < 8;
        if (cf) {
            int seen = 0;
            for (int i = 0; i < 4; ++i) {
                int bb = 1 << (arr[i] & 3);
                if (seen & bb) { cf = false; break; }
                seen |= bb;
            }
        }
        if (cf) return mask;
        if (fallback < 0) fallback = mask;
    }
    return fallback;
}

static GateMasks compute_masks()
{
    GateMasks g{};
    unsigned R[NW];
    for (int j = 0; j < NW; ++j) R[j] = 1u << j;
    // Entangler: CNOT(w, w+1) for w=0..12, then CNOT(13, 0). Wire w <-> bit 13-w.
    for (int w = 0; w < NW - 1; ++w) R[NW - 2 - w] ^= R[NW - 1 - w];
    R[NW - 1] ^= R[0];
    for (int j = 0; j < NW; ++j) g.rowA[j] = (int)R[j];

    // A^-1 via Gauss-Jordan over GF(2)
    unsigned aug[NW];
    for (int j = 0; j < NW; ++j) aug[j] = R[j] | (1u << (NW + j));
    for (int col = 0; col < NW; ++col) {
        int piv = -1;
        for (int rr = col; rr < NW; ++rr)
            if ((aug[rr] >> col) & 1u) { piv = rr; break; }
        unsigned tmp = aug[col]; aug[col] = aug[piv]; aug[piv] = tmp;
        for (int rr = 0; rr < NW; ++rr)
            if (rr != col && ((aug[rr] >> col) & 1u)) aug[rr] ^= aug[col];
    }
    for (int bcol = 0; bcol < NW; ++bcol) {
        unsigned mcol = 0;
        for (int j = 0; j < NW; ++j) mcol |= ((aug[j] >> (NW + bcol)) & 1u) << j;
        g.colAinv[bcol] = (int)mcol;
    }
    for (int k = 0; k < NW; ++k) {
        unsigned rr = 0;
        for (int j = 0; j < NW; ++j) if ((R[k] >> j) & 1u) rr ^= R[j];
        g.rowA2[k] = (int)rr;
    }

    // Complement positions for the three 4-bit passes and the 2-bit final pass.
    const int B0s[3] = {10, 6, 2};
    for (int pidx = 0; pidx < 3; ++pidx) {
        int cols[4];
        for (int i = 0; i < 4; ++i) cols[i] = g.colAinv[B0s[pidx] + i];
        const int T = chooseT(cols, 4);
        int n = 0;
        for (int p = 0; p < NW; ++p) if (!((T >> p) & 1)) g.pos[pidx][n++] = p;
    }
    {
        int cols[2] = { g.colAinv[0], g.colAinv[1] };
        const int T = chooseT(cols, 2);
        int n = 0;
        for (int p = 0; p < NW; ++p) if (!((T >> p) & 1)) g.pos[3][n++] = p;
    }
    g.sel0 = g.sel1 = 0;
    for (int w = 0; w < NW; ++w) {
        if (gf2par((unsigned)(g.rowA2[13 - w] & g.colAinv[0]))) g.sel0 |= 1 << w;
        if (gf2par((unsigned)(g.rowA2[13 - w] & g.colAinv[1]))) g.sel1 |= 1 << w;
    }
    return g;
}

extern "C" void kernel_launch(void* const* d_in, const int* in_sizes, int n_in,
                              void* d_out, int out_size)
{
    int i_x = 0, i_p = 1;
    if (n_in >= 2 && in_sizes[0] == 2 * NW * 3) { i_x = 1; i_p = 0; }
    const float* x = (const float*)d_in[i_x];
    const float* params = (const float*)d_in[i_p];
    float* out = (float*)d_out;

    const int batch = in_sizes[i_x] / NW;
    static const GateMasks gm = compute_masks();

    cudaFuncSetAttribute(qsim_kernel, cudaFuncAttributeMaxDynamicSharedMemorySize,
                         NSTATE * sizeof(float2));
    qsim_kernel<<<batch, NTHREADS, NSTATE * sizeof(float2)>>>(x, params, out, gm);
}

// round 4
// speedup vs baseline: 1.9908x; 1.9908x over previous
#include <cuda_runtime.h>

#define NW 14
#define NSTATE (1 << NW)        // 16384 amplitudes
#define NTHREADS 1024
#define NWARPS (NTHREADS / 32)

// ==================== compile-time GF(2) machinery ====================
// The entangler (ring of CNOTs) is FIXED, so the linear-map data (A, A^-1, A^2),
// coset masks, swizzled offsets and Walsh selectors are compile-time constants.
struct CT {
    unsigned rowA[NW];      // rows of A (virtual-bit parities)
    unsigned colAinv[NW];   // columns of A^-1 (pair masks)
    unsigned rowA2[NW];     // rows of A^2 (measurement parity masks)
    int pos[4][12];         // complement unit positions per pass
    unsigned swzM[3][16];   // swz(coset mask M_u) per 4-bit pass
    unsigned baseM[3][4];   // rowA rows for base parities per pass
    unsigned swzF[4];       // final pass: swz of {0, m0, m1, m0^m1}
    int sel[NW];            // Walsh selector per wire (2 bits)
    unsigned cw[NW];        // rowA2[13-w]
};

constexpr unsigned ctswz(unsigned y) { return y ^ ((y >> 4) & 0xFu); }
constexpr int ctpar(unsigned v) { int p = 0; while (v) { p ^= (int)(v & 1u); v >>= 1; } return p; }
constexpr int ctpop(unsigned v) { int p = 0; while (v) { p += (int)(v & 1u); v >>= 1; } return p; }

constexpr bool invOK(const unsigned* cols, int k, unsigned T) {
    int rows[4] = {0, 0, 0, 0}; int n = 0;
    for (int p = 0; p < NW; ++p) if ((T >> p) & 1u) { if (n < 4) rows[n] = p; ++n; }
    if (n != k) return false;
    unsigned mat[4] = {0, 0, 0, 0};
    for (int i = 0; i < k; ++i) {
        unsigned m = 0;
        for (int j = 0; j < k; ++j) m |= ((cols[j] >> rows[i]) & 1u) << j;
        mat[i] = m;
    }
    for (int c = 0; c < k; ++c) {
        int piv = -1;
        for (int rr = c; rr < k; ++rr) if ((mat[rr] >> c) & 1u) { piv = rr; break; }
        if (piv < 0) return false;
        unsigned t = mat[c]; mat[c] = mat[piv]; mat[piv] = t;
        for (int rr = 0; rr < k; ++rr)
            if (rr != c && ((mat[rr] >> c) & 1u)) mat[rr] ^= mat[c];
    }
    return true;
}

// Removal set T (|T|=k): submatrix invertible (correctness); prefer complements
// whose 4 lowest positions are <8 with distinct (p mod 4) so half-warp shared
// accesses are provably bank-conflict-free under the swizzle.
constexpr unsigned chooseT(const unsigned* cols, int k) {
    unsigned fb = 0; bool havefb = false;
    for (unsigned mask = 0; mask < (1u << NW); ++mask) {
        if (ctpop(mask) != k) continue;
        if (!invOK(cols, k, mask)) continue;
        int arr[NW] = {}; int n = 0;
        for (int p = 0; p < NW; ++p) if (!((mask >> p) & 1u)) arr[n++] = p;
        bool cf = arr[0] < 8 && arr[1] < 8 && arr[2] < 8 && arr[3] < 8;
        if (cf) {
            int seen = 0;
            for (int i = 0; i < 4; ++i) {
                int bb = 1 << (arr[i] & 3);
                if (seen & bb) { cf = false; break; }
                seen |= bb;
            }
        }
        if (cf) return mask;
        if (!havefb) { fb = mask; havefb = true; }
    }
    return fb;
}

constexpr CT buildCT() {
    CT g{};
    unsigned R[NW] = {};
    for (int j = 0; j < NW; ++j) R[j] = 1u << j;
    // CNOT(w, w+1) for w=0..12, then CNOT(13, 0); wire w <-> bit 13-w.
    for (int w = 0; w < NW - 1; ++w) R[NW - 2 - w] ^= R[NW - 1 - w];
    R[NW - 1] ^= R[0];
    for (int j = 0; j < NW; ++j) g.rowA[j] = R[j];
    // A^-1 via Gauss-Jordan over GF(2)
    unsigned aug[NW] = {};
    for (int j = 0; j < NW; ++j) aug[j] = R[j] | (1u << (NW + j));
    for (int col = 0; col < NW; ++col) {
        int piv = -1;
        for (int rr = col; rr < NW; ++rr)
            if ((aug[rr] >> col) & 1u) { piv = rr; break; }
        unsigned t = aug[col]; aug[col] = aug[piv]; aug[piv] = t;
        for (int rr = 0; rr < NW; ++rr)
            if (rr != col && ((aug[rr] >> col) & 1u)) aug[rr] ^= aug[col];
    }
    for (int bc = 0; bc < NW; ++bc) {
        unsigned mc = 0;
        for (int j = 0; j < NW; ++j) mc |= ((aug[j] >> (NW + bc)) & 1u) << j;
        g.colAinv[bc] = mc;
    }
    for (int k2 = 0; k2 < NW; ++k2) {
        unsigned rr = 0;
        for (int j = 0; j < NW; ++j) if ((R[k2] >> j) & 1u) rr ^= R[j];
        g.rowA2[k2] = rr;
    }
    const int B0s[3] = {10, 6, 2};
    for (int p = 0; p < 3; ++p) {
        unsigned cols[4] = {};
        for (int i = 0; i < 4; ++i) cols[i] = g.colAinv[B0s[p] + i];
        const unsigned T = chooseT(cols, 4);
        int n = 0;
        for (int q = 0; q < NW; ++q) if (!((T >> q) & 1u)) g.pos[p][n++] = q;
        for (unsigned u = 0; u < 16; ++u) {
            unsigned M = 0;
            for (int i = 0; i < 4; ++i) if ((u >> i) & 1u) M ^= cols[i];
            g.swzM[p][u] = ctswz(M);
        }
        for (int i = 0; i < 4; ++i) g.baseM[p][i] = g.rowA[B0s[p] + i];
    }
    {
        unsigned cols[4] = {g.colAinv[0], g.colAinv[1], 0, 0};
        const unsigned T = chooseT(cols, 2);
        int n = 0;
        for (int q = 0; q < NW; ++q) if (!((T >> q) & 1u)) g.pos[3][n++] = q;
        g.swzF[0] = 0;
        g.swzF[1] = ctswz(cols[0]);
        g.swzF[2] = ctswz(cols[1]);
        g.swzF[3] = ctswz(cols[0] ^ cols[1]);
        for (int w = 0; w < NW; ++w) {
            g.cw[w] = g.rowA2[13 - w];
            const int s0 = ctpar(cols[0] & g.cw[w]);
            const int s1 = ctpar(cols[1] & g.cw[w]);
            g.sel[w] = s0 | (s1 << 1);
        }
    }
    return g;
}

constexpr CT CD = buildCT();

// Device code must see CD only through template arguments (constant-expression
// context) -> values are baked into the instantiation as literals. No LDC.
template<int V> struct IC { static constexpr int v = V; };

// ==================== device helpers ====================
__device__ __forceinline__ float2 cmul(float2 a, float2 b) {
    return make_float2(fmaf(a.x, b.x, -a.y * b.y), fmaf(a.x, b.y, a.y * b.x));
}
__device__ __forceinline__ float2 cmadd(float2 acc, float2 a, float2 b) {
    acc.x = fmaf(a.x, b.x, fmaf(-a.y, b.y, acc.x));
    acc.y = fmaf(a.x, b.y, fmaf(a.y, b.x, acc.y));
    return acc;
}
__device__ __forceinline__ int dswz(int y) { return y ^ ((y >> 4) & 0xF); }

// r = scatter of tid bits to the pass's complement positions (immediates)
template<int P, int K>
__device__ __forceinline__ int build_r(int tid) {
    int v = ((tid >> K) & 1) << IC<CD.pos[P][K]>::v;
    if constexpr (K > 0) v |= build_r<P, K - 1>(tid);
    return v;
}
template<int P, int U>
__device__ __forceinline__ void coset_ld(float2 (&amp)[16], const float2* st, int zb) {
    amp[U] = st[zb ^ IC<(int)CD.swzM[P][U]>::v];
    if constexpr (U < 15) coset_ld<P, U + 1>(amp, st, zb);
}
template<int P, int U>
__device__ __forceinline__ void coset_st(const float2 (&amp)[16], float2* st, int zb) {
    st[zb ^ IC<(int)CD.swzM[P][U]>::v] = amp[U];
    if constexpr (U < 15) coset_st<P, U + 1>(amp, st, zb);
}

// One 4-bit gate pass. Addresses are pure swz(r)^const (bank-conflict-free by
// chooseT); base parities are folded into a matrix-element index swap (e^3).
template<int P>
__device__ __forceinline__ void gatepass(float2* state, const float2 (*m1)[4], int tid)
{
    constexpr int B0 = 10 - 4 * P;
    const int r = build_r<P, 9>(tid);
    const int zb = dswz(r);
    const int b0 = __popc(r & IC<(int)CD.baseM[P][0]>::v) & 1;
    const int b1 = __popc(r & IC<(int)CD.baseM[P][1]>::v) & 1;
    const int b2 = __popc(r & IC<(int)CD.baseM[P][2]>::v) & 1;
    const int b3 = __popc(r & IC<(int)CD.baseM[P][3]>::v) & 1;
    const int base = b0 | (b1 << 1) | (b2 << 2) | (b3 << 3);

    float2 amp[16];
    coset_ld<P, 0>(amp, state, zb);
#pragma unroll
    for (int i = 0; i < 4; ++i) {
        const int w = 13 - (B0 + i);
        const int sw = ((base >> i) & 1) ? 3 : 0;   // label swap -> reversed matrix
        const float2 E00 = m1[w][0 ^ sw], E01 = m1[w][1 ^ sw];
        const float2 E10 = m1[w][2 ^ sw], E11 = m1[w][3 ^ sw];
#pragma unroll
        for (int u = 0; u < 16; ++u) {
            if (u & (1 << i)) continue;
            float2 a0 = amp[u], a1 = amp[u | (1 << i)];
            float2 n0 = cmul(E00, a0); n0 = cmadd(n0, E01, a1);
            float2 n1 = cmul(E10, a0); n1 = cmadd(n1, E11, a1);
            amp[u] = n0; amp[u | (1 << i)] = n1;
        }
    }
    coset_st<P, 0>(amp, state, zb);
}

// Accumulate all 14 wires for one coset: acc[w] += (-1)^par(r&cw) * W[sel]
template<int W>
__device__ __forceinline__ void accw(float (&acc)[NW], int r,
                                     float W0, float W1, float W2, float W3) {
    constexpr int s = IC<CD.sel[W]>::v;
    const float tv = (s == 0) ? W0 : (s == 1) ? W1 : (s == 2) ? W2 : W3;
    const int sg = __popc(r & IC<(int)CD.cw[W]>::v) << 31;   // parity -> sign bit
    acc[W] += __int_as_float(__float_as_int(tv) ^ sg);
    if constexpr (W < NW - 1) accw<W + 1>(acc, r, W0, W1, W2, W3);
}

// ==================== kernel ====================
__global__ __launch_bounds__(NTHREADS, 1)
void qsim_kernel(const float* __restrict__ x, const float* __restrict__ params,
                 float* __restrict__ out)
{
    extern __shared__ float2 state[];      // 16384 float2 = 128 KB
    __shared__ float2 mats[2][NW][4];      // fused 2x2 per (layer, wire)
    __shared__ float wsum[NWARPS][NW];

    const int tid = threadIdx.x;
    const int b = blockIdx.x;

    // ---- fused gate matrices: M = RX * RZ * RY (layer 0 folds in x)
    if (tid < 2 * NW) {
        const int l = tid / NW, w = tid % NW;
        const float* pp = params + (l * NW + w) * 3;
        float th = pp[0] + (l == 0 ? x[b * NW + w] : 0.0f);
        float s, c;   sincosf(0.5f * th, &s, &c);
        float sz, cz; sincosf(0.5f * pp[1], &sz, &cz);
        float sx, cx; sincosf(0.5f * pp[2], &sx, &cx);
        float2 r00 = make_float2(c * cz, -c * sz);
        float2 r01 = make_float2(-s * cz, s * sz);
        float2 r10 = make_float2(s * cz, s * sz);
        float2 r11 = make_float2(c * cz, c * sz);
        mats[l][w][0] = make_float2(cx * r00.x + sx * r10.y, cx * r00.y - sx * r10.x);
        mats[l][w][1] = make_float2(cx * r01.x + sx * r11.y, cx * r01.y - sx * r11.x);
        mats[l][w][2] = make_float2(sx * r00.y + cx * r10.x, -sx * r00.x + cx * r10.y);
        mats[l][w][3] = make_float2(sx * r01.y + cx * r11.x, -sx * r01.x + cx * r11.y);
    }
    __syncthreads();

    // ---- Pass 0: build post-layer-0 product state (no loads, tree expansion)
    {
        const int t = tid;                              // y bits 4..13
        float2 p = mats[0][9][(t & 1) ? 2 : 0];         // y bit 4 = wire 9
#pragma unroll
        for (int bb = 5; bb < 14; ++bb) {
            float2 c = mats[0][13 - bb][((t >> (bb - 4)) & 1) ? 2 : 0];
            p = cmul(p, c);
        }
        float2 amp[16];
        amp[0] = p;
#pragma unroll
        for (int i = 0; i < 4; ++i) {                   // y bit i = wire 13-i
            const float2 c0 = mats[0][13 - i][0], c1 = mats[0][13 - i][2];
#pragma unroll
            for (int j = (1 << i) - 1; j >= 0; --j) {
                amp[j | (1 << i)] = cmul(amp[j], c1);
                amp[j] = cmul(amp[j], c0);
            }
        }
        const int sb = dswz(t << 4);                    // swz linear: offsets = j
#pragma unroll
        for (int j = 0; j < 16; ++j) state[sb ^ j] = amp[j];
    }
    __syncthreads();

    // ---- Three 4-bit gate passes (virtual bits {10..13}, {6..9}, {2..5})
    gatepass<0>(state, mats[1], tid);
    __syncthreads();
    gatepass<1>(state, mats[1], tid);
    __syncthreads();
    gatepass<2>(state, mats[1], tid);
    __syncthreads();

    // ---- Final pass: gates on virtual bits {0,1} fused with measurement
    float acc[NW];
#pragma unroll
    for (int w = 0; w < NW; ++w) acc[w] = 0.0f;
    {
        const int r0 = build_r<3, 9>(tid);
#pragma unroll
        for (int it = 0; it < 4; ++it) {
            int r = r0;
            if (it & 1) r ^= 1 << IC<CD.pos[3][10]>::v;
            if (it & 2) r ^= 1 << IC<CD.pos[3][11]>::v;
            const int z = dswz(r);
            const int b0 = __popc(r & IC<(int)CD.rowA[0]>::v) & 1;
            const int b1 = __popc(r & IC<(int)CD.rowA[1]>::v) & 1;
            // slot v at physical index r ^ {0, m0, m1, m0^m1}
            float2 a0 = state[z];
            float2 a1 = state[z ^ IC<(int)CD.swzF[1]>::v];
            float2 a2 = state[z ^ IC<(int)CD.swzF[2]>::v];
            float2 a3 = state[z ^ IC<(int)CD.swzF[3]>::v];
            {   // gate wire 13 (virtual bit 0): pairs (a0,a1), (a2,a3)
                const int sw = b0 ? 3 : 0;
                const float2 E00 = mats[1][13][0 ^ sw], E01 = mats[1][13][1 ^ sw];
                const float2 E10 = mats[1][13][2 ^ sw], E11 = mats[1][13][3 ^ sw];
                float2 n0 = cmul(E00, a0); n0 = cmadd(n0, E01, a1);
                float2 n1 = cmul(E10, a0); n1 = cmadd(n1, E11, a1);
                float2 n2 = cmul(E00, a2); n2 = cmadd(n2, E01, a3);
                float2 n3 = cmul(E10, a2); n3 = cmadd(n3, E11, a3);
                a0 = n0; a1 = n1; a2 = n2; a3 = n3;
            }
            {   // gate wire 12 (virtual bit 1): pairs (a0,a2), (a1,a3)
                const int sw = b1 ? 3 : 0;
                const float2 E00 = mats[1][12][0 ^ sw], E01 = mats[1][12][1 ^ sw];
                const float2 E10 = mats[1][12][2 ^ sw], E11 = mats[1][12][3 ^ sw];
                float2 n0 = cmul(E00, a0); n0 = cmadd(n0, E01, a2);
                float2 n2 = cmul(E10, a0); n2 = cmadd(n2, E11, a2);
                float2 n1 = cmul(E00, a1); n1 = cmadd(n1, E01, a3);
                float2 n3 = cmul(E10, a1); n3 = cmadd(n3, E11, a3);
                a0 = n0; a2 = n2; a1 = n1; a3 = n3;
            }
            const float p0 = fmaf(a0.x, a0.x, a0.y * a0.y);
            const float p1 = fmaf(a1.x, a1.x, a1.y * a1.y);
            const float p2 = fmaf(a2.x, a2.x, a2.y * a2.y);
            const float p3 = fmaf(a3.x, a3.x, a3.y * a3.y);
            const float sa = p0 + p1, sb = p0 - p1, sc = p2 + p3, sd = p2 - p3;
            const float W0 = sa + sc, W1 = sb + sd, W2 = sa - sc, W3 = sb - sd;
            accw<0>(acc, r, W0, W1, W2, W3);
        }
    }

    // ---- block reduction of 14 accumulators
    const int lane = tid & 31, warp = tid >> 5;
#pragma unroll
    for (int w = 0; w < NW; ++w) {
        float v = acc[w];
#pragma unroll
        for (int off = 16; off; off >>= 1) v += __shfl_down_sync(0xFFFFFFFFu, v, off);
        if (lane == 0) wsum[warp][w] = v;
    }
    __syncthreads();
    if (tid < NW) {
        float s = 0.0f;
#pragma unroll
        for (int q = 0; q < NWARPS; ++q) s += wsum[q][tid];
        out[b * NW + tid] = s;
    }
}

// ==================== host side ====================
extern "C" void kernel_launch(void* const* d_in, const int* in_sizes, int n_in,
                              void* d_out, int out_size)
{
    int i_x = 0, i_p = 1;
    if (n_in >= 2 && in_sizes[0] == 2 * NW * 3) { i_x = 1; i_p = 0; }
    const float* x = (const float*)d_in[i_x];
    const float* params = (const float*)d_in[i_p];
    float* out = (float*)d_out;

    const int batch = in_sizes[i_x] / NW;

    cudaFuncSetAttribute(qsim_kernel, cudaFuncAttributeMaxDynamicSharedMemorySize,
                         NSTATE * sizeof(float2));
    qsim_kernel<<<batch, NTHREADS, NSTATE * sizeof(float2)>>>(x, params, out);
}